// round 15
// baseline (speedup 1.0000x reference)
#include <cuda_runtime.h>
#include <cstdint>
#include <cstddef>

// Butterfly transform: B=8192 rows, N=4096, 12 stages, increasing stride.
// R15 = R14 (best, 74.8us: quad packing, 192KB smem, persistent 148 CTAs,
// balanced 568x12 + 172x8 tiles, L2 prefetch, phase-scoped + hoisted twiddle
// caches, streaming ld/st hints) + cross-tile register preload:
//   After phase 3's smem reads (tw3/data regs dying), issue the NEXT tile's
//   quad-0 LDGs into registers BEFORE the end-of-tile barrier. Their L2-hit
//   latency drains under the STG drain + barrier + tw0 loads, so the next
//   tile's phase 0 starts with FMA-ready data for q=0 while q=1,2 load.

namespace {
constexpr int kN       = 4096;
constexpr int kBatch   = 8192;
constexpr int kThreads = 512;
constexpr int kTiles12 = 568;                               // 12-row tiles
constexpr int kTiles   = 740;                               // = 148 * 5
constexpr int kGrid    = 148;                               // persistent
constexpr int kSmem    = 3 * kN * (int)sizeof(float4);      // 196608 B
}

// float4-granule swizzle: XOR low-3 index bits with bits 3..5.
__device__ __forceinline__ int swz(int i) { return i ^ ((i >> 3) & 7); }

__device__ __forceinline__ void prefetch_l2(const void* p) {
    asm volatile("prefetch.global.L2 [%0];" :: "l"(p));
}

// Row offset and row count for tile index i.
__device__ __forceinline__ int tile_row0(int i) {
    return (i < kTiles12) ? 12 * i : 12 * kTiles12 + 8 * (i - kTiles12);
}
__device__ __forceinline__ int tile_rows(int i) {
    return (i < kTiles12) ? 12 : 8;
}

// Load quad-0 raw data (rows row0..row0+3, elements 8t..8t+7) into regs.
__device__ __forceinline__ void preload_quad(const float* __restrict__ x,
                                             int row0, int t,
                                             float4 pre[4][2]) {
    #pragma unroll
    for (int j = 0; j < 4; ++j) {
        const float4* xr = reinterpret_cast<const float4*>(
            x + (size_t)(row0 + j) * kN);
        pre[j][0] = __ldcs(xr + 2 * t);    // read-once: evict-first
        pre[j][1] = __ldcs(xr + 2 * t + 1);
    }
}

// One 2x2 butterfly applied to four rows packed in float4 lanes.
__device__ __forceinline__ void bfly(float4& x0, float4& x1, const float4 tm) {
    float4 y0, y1;
    y0.x = __fmaf_rn(tm.y, x1.x, tm.x * x0.x);
    y0.y = __fmaf_rn(tm.y, x1.y, tm.x * x0.y);
    y0.z = __fmaf_rn(tm.y, x1.z, tm.x * x0.z);
    y0.w = __fmaf_rn(tm.y, x1.w, tm.x * x0.w);
    y1.x = __fmaf_rn(tm.w, x1.x, tm.z * x0.x);
    y1.y = __fmaf_rn(tm.w, x1.y, tm.z * x0.y);
    y1.z = __fmaf_rn(tm.w, x1.z, tm.z * x0.z);
    y1.w = __fmaf_rn(tm.w, x1.w, tm.z * x0.w);
    x0 = y0;
    x1 = y1;
}

// Three in-register substages over 8 owned elements (local strides 1,2,4).
__device__ __forceinline__ void substages(float4 v[8], const float4 twr[3][4]) {
    bfly(v[0], v[1], twr[0][0]); bfly(v[2], v[3], twr[0][1]);
    bfly(v[4], v[5], twr[0][2]); bfly(v[6], v[7], twr[0][3]);
    bfly(v[0], v[2], twr[1][0]); bfly(v[1], v[3], twr[1][1]);
    bfly(v[4], v[6], twr[1][2]); bfly(v[5], v[7], twr[1][3]);
    bfly(v[0], v[4], twr[2][0]); bfly(v[1], v[5], twr[2][1]);
    bfly(v[2], v[6], twr[2][2]); bfly(v[3], v[7], twr[2][3]);
}

// Transpose 4 rows x 8 elements (2 float4 per row) into row-packed elements.
__device__ __forceinline__ void pack_quad(const float4 r[4][2], float4 v[8]) {
    v[0] = make_float4(r[0][0].x, r[1][0].x, r[2][0].x, r[3][0].x);
    v[1] = make_float4(r[0][0].y, r[1][0].y, r[2][0].y, r[3][0].y);
    v[2] = make_float4(r[0][0].z, r[1][0].z, r[2][0].z, r[3][0].z);
    v[3] = make_float4(r[0][0].w, r[1][0].w, r[2][0].w, r[3][0].w);
    v[4] = make_float4(r[0][1].x, r[1][1].x, r[2][1].x, r[3][1].x);
    v[5] = make_float4(r[0][1].y, r[1][1].y, r[2][1].y, r[3][1].y);
    v[6] = make_float4(r[0][1].z, r[1][1].z, r[2][1].z, r[3][1].z);
    v[7] = make_float4(r[0][1].w, r[1][1].w, r[2][1].w, r[3][1].w);
}

template <int NQ>
__device__ __forceinline__ void bf_body(const float* __restrict__ x,
                                        const float* __restrict__ tw,
                                        float* __restrict__ out,
                                        int row0, int nrow0, int nchunks,
                                        int prow0, float4* buf,
                                        float4 pre[4][2]) {
    const int t = threadIdx.x;
    const float4* tw4 = reinterpret_cast<const float4*>(tw);

    // ---------------- Phase 0: stages 0..2 (strides 1,2,4) ----------------
    {
        float4 twr[3][4];
        #pragma unroll
        for (int u = 0; u < 3; ++u)
            #pragma unroll
            for (int pm = 0; pm < 4; ++pm)
                twr[u][pm] = tw4[u * 2048 + 4 * t + pm];
        int off[8];
        #pragma unroll
        for (int m = 0; m < 8; ++m) off[m] = swz(8 * t + m);

        // q = 0: data preloaded into registers before last tile's end barrier.
        {
            float4 v[8];
            pack_quad(pre, v);
            substages(v, twr);
            #pragma unroll
            for (int m = 0; m < 8; ++m) buf[off[m]] = v[m];
        }

        #pragma unroll
        for (int q = 1; q < NQ; ++q) {
            float4 r[4][2];
            #pragma unroll
            for (int j = 0; j < 4; ++j) {
                const float4* xr = reinterpret_cast<const float4*>(
                    x + (size_t)(row0 + 4 * q + j) * kN);
                r[j][0] = __ldcs(xr + 2 * t);
                r[j][1] = __ldcs(xr + 2 * t + 1);
            }
            float4 v[8];
            pack_quad(r, v);
            substages(v, twr);
            float4* B = buf + q * kN;
            #pragma unroll
            for (int m = 0; m < 8; ++m) B[off[m]] = v[m];
        }
    }

    // ---- HOISTED: phase-1 twiddle loads drain L2 latency during barrier.
    const int b1 = t >> 3, c1 = t & 7;                    // s = 8
    float4 tw1[3][4];
    #pragma unroll
    for (int u = 0; u < 3; ++u)
        #pragma unroll
        for (int pm = 0; pm < 4; ++pm)
            tw1[u][pm] = tw4[(3 + u) * 2048 + 8 * (4 * b1 + pm) + c1];

    __syncthreads();

    // ------------- Phase 1: stages 3..5 (strides 8,16,32), smem -----------
    {
        int off[8];
        #pragma unroll
        for (int m = 0; m < 8; ++m) off[m] = swz(b1 * 64 + c1 + 8 * m);

        // Prefetch the NEXT tile's data into L2 under phases 1-3 compute.
        if (nrow0 >= 0) {
            const char* nb = reinterpret_cast<const char*>(
                x + (size_t)nrow0 * kN);
            #pragma unroll
            for (int k = 0; k < 3; ++k) {
                const int idx = t + 512 * k;
                if (idx < nchunks)
                    prefetch_l2(nb + (size_t)idx * 128);
            }
        }

        #pragma unroll
        for (int q = 0; q < NQ; ++q) {
            float4* B = buf + q * kN;
            float4 v[8];
            #pragma unroll
            for (int m = 0; m < 8; ++m) v[m] = B[off[m]];

            substages(v, tw1);

            #pragma unroll
            for (int m = 0; m < 8; ++m) B[off[m]] = v[m];
        }
    }

    // ---- HOISTED: phase-2 twiddle loads before the barrier.
    const int b2 = t >> 6, c2 = t & 63;                   // s = 64
    float4 tw2[3][4];
    #pragma unroll
    for (int u = 0; u < 3; ++u)
        #pragma unroll
        for (int pm = 0; pm < 4; ++pm)
            tw2[u][pm] = tw4[(6 + u) * 2048 + 64 * (4 * b2 + pm) + c2];

    __syncthreads();

    // ------------- Phase 2: stages 6..8 (strides 64,128,256), smem --------
    {
        int off[8];
        #pragma unroll
        for (int m = 0; m < 8; ++m) off[m] = swz(b2 * 512 + c2 + 64 * m);

        #pragma unroll
        for (int q = 0; q < NQ; ++q) {
            float4* B = buf + q * kN;
            float4 v[8];
            #pragma unroll
            for (int m = 0; m < 8; ++m) v[m] = B[off[m]];

            substages(v, tw2);

            #pragma unroll
            for (int m = 0; m < 8; ++m) B[off[m]] = v[m];
        }
    }

    // ---- HOISTED: phase-3 twiddle loads before the barrier.
    float4 tw3[3][4];
    #pragma unroll
    for (int u = 0; u < 3; ++u)
        #pragma unroll
        for (int pm = 0; pm < 4; ++pm)
            tw3[u][pm] = tw4[(9 + u) * 2048 + 512 * pm + t];

    __syncthreads();

    // ------------- Phase 3: stages 9..11 (strides 512..2048) -> out -------
    {
        const int s = 512;  // b = 0, c = t
        int off[8];
        #pragma unroll
        for (int m = 0; m < 8; ++m) off[m] = swz(t + s * m);

        #pragma unroll
        for (int q = 0; q < NQ; ++q) {
            float4* B = buf + q * kN;
            float4 v[8];
            #pragma unroll
            for (int m = 0; m < 8; ++m) v[m] = B[off[m]];

            substages(v, tw3);

            float* o0 = out + (size_t)(row0 + 4 * q) * kN;
            float* o1 = o0 + kN;
            float* o2 = o1 + kN;
            float* o3 = o2 + kN;
            #pragma unroll
            for (int m = 0; m < 8; ++m) {
                __stcs(o0 + t + s * m, v[m].x);   // write-once: streaming
                __stcs(o1 + t + s * m, v[m].y);
                __stcs(o2 + t + s * m, v[m].z);
                __stcs(o3 + t + s * m, v[m].w);
            }
        }
    }

    // ---- Cross-tile preload: next tile's quad-0 LDGs issued before the
    // ---- end-of-tile barrier; latency drains under STG drain + barrier.
    preload_quad(x, prow0, t, pre);

    __syncthreads();   // slots reused by next tile's phase 0
}

__global__ void __launch_bounds__(kThreads, 1)
butterfly_kernel(const float* __restrict__ x,
                 const float* __restrict__ tw,
                 float* __restrict__ out) {
    extern __shared__ float4 buf[];
    const int t = threadIdx.x;

    // Prime the preload with this CTA's first tile, quad 0.
    float4 pre[4][2];
    preload_quad(x, tile_row0(blockIdx.x), t, pre);

    for (int tile = blockIdx.x; tile < kTiles; tile += kGrid) {
        const int row0  = tile_row0(tile);
        const int nt    = tile + kGrid;
        const int nrow0 = (nt < kTiles) ? tile_row0(nt) : -1;
        const int nchk  = (nt < kTiles) ? tile_rows(nt) * (kN * 4 / 128) : 0;
        const int prow0 = (nrow0 >= 0) ? nrow0 : row0;   // clamp: benign reload

        if (tile < kTiles12) {
            bf_body<3>(x, tw, out, row0, nrow0, nchk, prow0, buf, pre);
        } else {
            bf_body<2>(x, tw, out, row0, nrow0, nchk, prow0, buf, pre);
        }
    }
}

extern "C" void kernel_launch(void* const* d_in, const int* in_sizes, int n_in,
                              void* d_out, int out_size) {
    const float* x  = (const float*)d_in[0];   // (8192, 4096) fp32
    const float* tw = (const float*)d_in[1];   // (1,1,12,2048,2,2) fp32
    float* out      = (float*)d_out;           // (8192, 4096) fp32

    cudaFuncSetAttribute(butterfly_kernel,
                         cudaFuncAttributeMaxDynamicSharedMemorySize, kSmem);
    butterfly_kernel<<<kGrid, kThreads, kSmem>>>(x, tw, out);
}

// round 16
// speedup vs baseline: 1.0319x; 1.0319x over previous
#include <cuda_runtime.h>
#include <cstdint>
#include <cstddef>

// Butterfly transform: B=8192 rows, N=4096, 12 stages, increasing stride.
// R16 = R14 (best, 74.8us) with ONE change: the end-of-tile barrier moves
// from after all of phase 3 to immediately after the LAST quad's smem reads.
// The last quad's 12 butterflies + 32 STGs then overlap the next tile's
// phase-0 LDGs/twiddle loads instead of serializing before the barrier.
// No extra registers live across the barrier (R15 lesson). Correctness:
// every thread's phase-3 smem reads precede its barrier in program order,
// so all reads complete CTA-wide before any next-tile phase-0 smem write.
// Everything else is byte-identical R14: quad packing, 192KB smem,
// persistent 148 CTAs, balanced 568x12 + 172x8 tiles (148x5), L2 prefetch,
// phase-scoped + hoisted twiddle caches, streaming ld/st hints.

namespace {
constexpr int kN       = 4096;
constexpr int kBatch   = 8192;
constexpr int kThreads = 512;
constexpr int kTiles12 = 568;                               // 12-row tiles
constexpr int kTiles   = 740;                               // = 148 * 5
constexpr int kGrid    = 148;                               // persistent
constexpr int kSmem    = 3 * kN * (int)sizeof(float4);      // 196608 B
}

// float4-granule swizzle: XOR low-3 index bits with bits 3..5.
__device__ __forceinline__ int swz(int i) { return i ^ ((i >> 3) & 7); }

__device__ __forceinline__ void prefetch_l2(const void* p) {
    asm volatile("prefetch.global.L2 [%0];" :: "l"(p));
}

// Row offset and row count for tile index i.
__device__ __forceinline__ int tile_row0(int i) {
    return (i < kTiles12) ? 12 * i : 12 * kTiles12 + 8 * (i - kTiles12);
}
__device__ __forceinline__ int tile_rows(int i) {
    return (i < kTiles12) ? 12 : 8;
}

// One 2x2 butterfly applied to four rows packed in float4 lanes.
__device__ __forceinline__ void bfly(float4& x0, float4& x1, const float4 tm) {
    float4 y0, y1;
    y0.x = __fmaf_rn(tm.y, x1.x, tm.x * x0.x);
    y0.y = __fmaf_rn(tm.y, x1.y, tm.x * x0.y);
    y0.z = __fmaf_rn(tm.y, x1.z, tm.x * x0.z);
    y0.w = __fmaf_rn(tm.y, x1.w, tm.x * x0.w);
    y1.x = __fmaf_rn(tm.w, x1.x, tm.z * x0.x);
    y1.y = __fmaf_rn(tm.w, x1.y, tm.z * x0.y);
    y1.z = __fmaf_rn(tm.w, x1.z, tm.z * x0.z);
    y1.w = __fmaf_rn(tm.w, x1.w, tm.z * x0.w);
    x0 = y0;
    x1 = y1;
}

// Three in-register substages over 8 owned elements (local strides 1,2,4).
__device__ __forceinline__ void substages(float4 v[8], const float4 twr[3][4]) {
    bfly(v[0], v[1], twr[0][0]); bfly(v[2], v[3], twr[0][1]);
    bfly(v[4], v[5], twr[0][2]); bfly(v[6], v[7], twr[0][3]);
    bfly(v[0], v[2], twr[1][0]); bfly(v[1], v[3], twr[1][1]);
    bfly(v[4], v[6], twr[1][2]); bfly(v[5], v[7], twr[1][3]);
    bfly(v[0], v[4], twr[2][0]); bfly(v[1], v[5], twr[2][1]);
    bfly(v[2], v[6], twr[2][2]); bfly(v[3], v[7], twr[2][3]);
}

// Transpose 4 rows x 8 elements (2 float4 per row) into row-packed elements.
__device__ __forceinline__ void pack_quad(const float4 r[4][2], float4 v[8]) {
    v[0] = make_float4(r[0][0].x, r[1][0].x, r[2][0].x, r[3][0].x);
    v[1] = make_float4(r[0][0].y, r[1][0].y, r[2][0].y, r[3][0].y);
    v[2] = make_float4(r[0][0].z, r[1][0].z, r[2][0].z, r[3][0].z);
    v[3] = make_float4(r[0][0].w, r[1][0].w, r[2][0].w, r[3][0].w);
    v[4] = make_float4(r[0][1].x, r[1][1].x, r[2][1].x, r[3][1].x);
    v[5] = make_float4(r[0][1].y, r[1][1].y, r[2][1].y, r[3][1].y);
    v[6] = make_float4(r[0][1].z, r[1][1].z, r[2][1].z, r[3][1].z);
    v[7] = make_float4(r[0][1].w, r[1][1].w, r[2][1].w, r[3][1].w);
}

// Phase-3 output: warp-contiguous streaming stores of one quad.
__device__ __forceinline__ void store_quad(float* __restrict__ out,
                                           int rowA, int t, const float4 v[8]) {
    float* o0 = out + (size_t)rowA * kN;
    float* o1 = o0 + kN;
    float* o2 = o1 + kN;
    float* o3 = o2 + kN;
    #pragma unroll
    for (int m = 0; m < 8; ++m) {
        __stcs(o0 + t + 512 * m, v[m].x);
        __stcs(o1 + t + 512 * m, v[m].y);
        __stcs(o2 + t + 512 * m, v[m].z);
        __stcs(o3 + t + 512 * m, v[m].w);
    }
}

template <int NQ>
__device__ __forceinline__ void bf_body(const float* __restrict__ x,
                                        const float* __restrict__ tw,
                                        float* __restrict__ out,
                                        int row0, int nrow0, int nchunks,
                                        float4* buf) {
    const int t = threadIdx.x;
    const float4* tw4 = reinterpret_cast<const float4*>(tw);

    // ---------------- Phase 0: stages 0..2 (strides 1,2,4) ----------------
    {
        float4 twr[3][4];
        #pragma unroll
        for (int u = 0; u < 3; ++u)
            #pragma unroll
            for (int pm = 0; pm < 4; ++pm)
                twr[u][pm] = tw4[u * 2048 + 4 * t + pm];
        int off[8];
        #pragma unroll
        for (int m = 0; m < 8; ++m) off[m] = swz(8 * t + m);

        #pragma unroll
        for (int q = 0; q < NQ; ++q) {
            float4 r[4][2];
            #pragma unroll
            for (int j = 0; j < 4; ++j) {
                const float4* xr = reinterpret_cast<const float4*>(
                    x + (size_t)(row0 + 4 * q + j) * kN);
                r[j][0] = __ldcs(xr + 2 * t);       // read-once: evict-first
                r[j][1] = __ldcs(xr + 2 * t + 1);
            }
            float4 v[8];
            pack_quad(r, v);
            substages(v, twr);
            float4* B = buf + q * kN;
            #pragma unroll
            for (int m = 0; m < 8; ++m) B[off[m]] = v[m];
        }
    }

    // ---- HOISTED: phase-1 twiddle loads drain L2 latency during barrier.
    const int b1 = t >> 3, c1 = t & 7;                    // s = 8
    float4 tw1[3][4];
    #pragma unroll
    for (int u = 0; u < 3; ++u)
        #pragma unroll
        for (int pm = 0; pm < 4; ++pm)
            tw1[u][pm] = tw4[(3 + u) * 2048 + 8 * (4 * b1 + pm) + c1];

    __syncthreads();

    // ------------- Phase 1: stages 3..5 (strides 8,16,32), smem -----------
    {
        int off[8];
        #pragma unroll
        for (int m = 0; m < 8; ++m) off[m] = swz(b1 * 64 + c1 + 8 * m);

        // Prefetch the NEXT tile's data into L2 under phases 1-3 compute.
        if (nrow0 >= 0) {
            const char* nb = reinterpret_cast<const char*>(
                x + (size_t)nrow0 * kN);
            #pragma unroll
            for (int k = 0; k < 3; ++k) {
                const int idx = t + 512 * k;
                if (idx < nchunks)
                    prefetch_l2(nb + (size_t)idx * 128);
            }
        }

        #pragma unroll
        for (int q = 0; q < NQ; ++q) {
            float4* B = buf + q * kN;
            float4 v[8];
            #pragma unroll
            for (int m = 0; m < 8; ++m) v[m] = B[off[m]];

            substages(v, tw1);

            #pragma unroll
            for (int m = 0; m < 8; ++m) B[off[m]] = v[m];
        }
    }

    // ---- HOISTED: phase-2 twiddle loads before the barrier.
    const int b2 = t >> 6, c2 = t & 63;                   // s = 64
    float4 tw2[3][4];
    #pragma unroll
    for (int u = 0; u < 3; ++u)
        #pragma unroll
        for (int pm = 0; pm < 4; ++pm)
            tw2[u][pm] = tw4[(6 + u) * 2048 + 64 * (4 * b2 + pm) + c2];

    __syncthreads();

    // ------------- Phase 2: stages 6..8 (strides 64,128,256), smem --------
    {
        int off[8];
        #pragma unroll
        for (int m = 0; m < 8; ++m) off[m] = swz(b2 * 512 + c2 + 64 * m);

        #pragma unroll
        for (int q = 0; q < NQ; ++q) {
            float4* B = buf + q * kN;
            float4 v[8];
            #pragma unroll
            for (int m = 0; m < 8; ++m) v[m] = B[off[m]];

            substages(v, tw2);

            #pragma unroll
            for (int m = 0; m < 8; ++m) B[off[m]] = v[m];
        }
    }

    // ---- HOISTED: phase-3 twiddle loads before the barrier.
    float4 tw3[3][4];
    #pragma unroll
    for (int u = 0; u < 3; ++u)
        #pragma unroll
        for (int pm = 0; pm < 4; ++pm)
            tw3[u][pm] = tw4[(9 + u) * 2048 + 512 * pm + t];

    __syncthreads();

    // ------------- Phase 3: stages 9..11 (strides 512..2048) -> out -------
    {
        int off[8];
        #pragma unroll
        for (int m = 0; m < 8; ++m) off[m] = swz(t + 512 * m);

        // Quads 0..NQ-2: read, compute, store.
        #pragma unroll
        for (int q = 0; q < NQ - 1; ++q) {
            float4* B = buf + q * kN;
            float4 v[8];
            #pragma unroll
            for (int m = 0; m < 8; ++m) v[m] = B[off[m]];

            substages(v, tw3);
            store_quad(out, row0 + 4 * q, t, v);
        }

        // Last quad: read smem, THEN the end-of-tile barrier (all smem reads
        // of this tile are now complete CTA-wide), then compute + store —
        // overlapping the next tile's phase-0 LDGs and twiddle loads.
        {
            float4* B = buf + (NQ - 1) * kN;
            float4 v[8];
            #pragma unroll
            for (int m = 0; m < 8; ++m) v[m] = B[off[m]];

            __syncthreads();   // slots now safe for next tile's phase 0

            substages(v, tw3);
            store_quad(out, row0 + 4 * (NQ - 1), t, v);
        }
    }
}

__global__ void __launch_bounds__(kThreads, 1)
butterfly_kernel(const float* __restrict__ x,
                 const float* __restrict__ tw,
                 float* __restrict__ out) {
    extern __shared__ float4 buf[];

    for (int tile = blockIdx.x; tile < kTiles; tile += kGrid) {
        const int row0  = tile_row0(tile);
        const int nt    = tile + kGrid;
        const int nrow0 = (nt < kTiles) ? tile_row0(nt) : -1;
        const int nchk  = (nt < kTiles) ? tile_rows(nt) * (kN * 4 / 128) : 0;

        if (tile < kTiles12) {
            bf_body<3>(x, tw, out, row0, nrow0, nchk, buf);   // 12-row tile
        } else {
            bf_body<2>(x, tw, out, row0, nrow0, nchk, buf);   // 8-row tile
        }
    }
}

extern "C" void kernel_launch(void* const* d_in, const int* in_sizes, int n_in,
                              void* d_out, int out_size) {
    const float* x  = (const float*)d_in[0];   // (8192, 4096) fp32
    const float* tw = (const float*)d_in[1];   // (1,1,12,2048,2,2) fp32
    float* out      = (float*)d_out;           // (8192, 4096) fp32

    cudaFuncSetAttribute(butterfly_kernel,
                         cudaFuncAttributeMaxDynamicSharedMemorySize, kSmem);
    butterfly_kernel<<<kGrid, kThreads, kSmem>>>(x, tw, out);
}

// round 17
// speedup vs baseline: 1.0912x; 1.0575x over previous
#include <cuda_runtime.h>
#include <cstdint>
#include <cstddef>

// Butterfly transform: B=8192 rows, N=4096, 12 stages, increasing stride.
// R17 = R16 (best, 74.2us) with barrier-scope reduction:
//  - ph0->1 exchange is WARP-LOCAL (phase-1 reads [256w,256w+255], exactly
//    what warp w wrote in phase 0) -> __syncwarp instead of __syncthreads.
//  - ph1->2 exchange is WARP-PAIR-LOCAL (phase-2 reads [512j,512j+511],
//    written by warps 2j,2j+1) -> named bar.sync(1+pair, 64).
//  - ph2->3 and end-of-tile barriers stay CTA-wide (stride-512 reads span N).
// Zero extra registers, zero extra ops: warps flow independently through
// phases 0-1, in pairs through 1-2; 16-warp convoy only twice per tile.
// Everything else byte-identical R16: quad packing, 192KB smem, persistent
// 148 CTAs, balanced 568x12 + 172x8 tiles (148x5), L2 prefetch, phase-scoped
// hoisted twiddle caches, streaming ld/st, late end-of-tile barrier.

namespace {
constexpr int kN       = 4096;
constexpr int kBatch   = 8192;
constexpr int kThreads = 512;
constexpr int kTiles12 = 568;                               // 12-row tiles
constexpr int kTiles   = 740;                               // = 148 * 5
constexpr int kGrid    = 148;                               // persistent
constexpr int kSmem    = 3 * kN * (int)sizeof(float4);      // 196608 B
}

// float4-granule swizzle: XOR low-3 index bits with bits 3..5.
__device__ __forceinline__ int swz(int i) { return i ^ ((i >> 3) & 7); }

__device__ __forceinline__ void prefetch_l2(const void* p) {
    asm volatile("prefetch.global.L2 [%0];" :: "l"(p));
}

// Warp-pair barrier: warps 2j,2j+1 sync on named barrier 1+j (64 threads).
__device__ __forceinline__ void bar_pair(int pair) {
    asm volatile("bar.sync %0, 64;" :: "r"(1 + pair) : "memory");
}

// Row offset and row count for tile index i.
__device__ __forceinline__ int tile_row0(int i) {
    return (i < kTiles12) ? 12 * i : 12 * kTiles12 + 8 * (i - kTiles12);
}
__device__ __forceinline__ int tile_rows(int i) {
    return (i < kTiles12) ? 12 : 8;
}

// One 2x2 butterfly applied to four rows packed in float4 lanes.
__device__ __forceinline__ void bfly(float4& x0, float4& x1, const float4 tm) {
    float4 y0, y1;
    y0.x = __fmaf_rn(tm.y, x1.x, tm.x * x0.x);
    y0.y = __fmaf_rn(tm.y, x1.y, tm.x * x0.y);
    y0.z = __fmaf_rn(tm.y, x1.z, tm.x * x0.z);
    y0.w = __fmaf_rn(tm.y, x1.w, tm.x * x0.w);
    y1.x = __fmaf_rn(tm.w, x1.x, tm.z * x0.x);
    y1.y = __fmaf_rn(tm.w, x1.y, tm.z * x0.y);
    y1.z = __fmaf_rn(tm.w, x1.z, tm.z * x0.z);
    y1.w = __fmaf_rn(tm.w, x1.w, tm.z * x0.w);
    x0 = y0;
    x1 = y1;
}

// Three in-register substages over 8 owned elements (local strides 1,2,4).
__device__ __forceinline__ void substages(float4 v[8], const float4 twr[3][4]) {
    bfly(v[0], v[1], twr[0][0]); bfly(v[2], v[3], twr[0][1]);
    bfly(v[4], v[5], twr[0][2]); bfly(v[6], v[7], twr[0][3]);
    bfly(v[0], v[2], twr[1][0]); bfly(v[1], v[3], twr[1][1]);
    bfly(v[4], v[6], twr[1][2]); bfly(v[5], v[7], twr[1][3]);
    bfly(v[0], v[4], twr[2][0]); bfly(v[1], v[5], twr[2][1]);
    bfly(v[2], v[6], twr[2][2]); bfly(v[3], v[7], twr[2][3]);
}

// Transpose 4 rows x 8 elements (2 float4 per row) into row-packed elements.
__device__ __forceinline__ void pack_quad(const float4 r[4][2], float4 v[8]) {
    v[0] = make_float4(r[0][0].x, r[1][0].x, r[2][0].x, r[3][0].x);
    v[1] = make_float4(r[0][0].y, r[1][0].y, r[2][0].y, r[3][0].y);
    v[2] = make_float4(r[0][0].z, r[1][0].z, r[2][0].z, r[3][0].z);
    v[3] = make_float4(r[0][0].w, r[1][0].w, r[2][0].w, r[3][0].w);
    v[4] = make_float4(r[0][1].x, r[1][1].x, r[2][1].x, r[3][1].x);
    v[5] = make_float4(r[0][1].y, r[1][1].y, r[2][1].y, r[3][1].y);
    v[6] = make_float4(r[0][1].z, r[1][1].z, r[2][1].z, r[3][1].z);
    v[7] = make_float4(r[0][1].w, r[1][1].w, r[2][1].w, r[3][1].w);
}

// Phase-3 output: warp-contiguous streaming stores of one quad.
__device__ __forceinline__ void store_quad(float* __restrict__ out,
                                           int rowA, int t, const float4 v[8]) {
    float* o0 = out + (size_t)rowA * kN;
    float* o1 = o0 + kN;
    float* o2 = o1 + kN;
    float* o3 = o2 + kN;
    #pragma unroll
    for (int m = 0; m < 8; ++m) {
        __stcs(o0 + t + 512 * m, v[m].x);
        __stcs(o1 + t + 512 * m, v[m].y);
        __stcs(o2 + t + 512 * m, v[m].z);
        __stcs(o3 + t + 512 * m, v[m].w);
    }
}

template <int NQ>
__device__ __forceinline__ void bf_body(const float* __restrict__ x,
                                        const float* __restrict__ tw,
                                        float* __restrict__ out,
                                        int row0, int nrow0, int nchunks,
                                        float4* buf) {
    const int t = threadIdx.x;
    const float4* tw4 = reinterpret_cast<const float4*>(tw);

    // ---------------- Phase 0: stages 0..2 (strides 1,2,4) ----------------
    {
        float4 twr[3][4];
        #pragma unroll
        for (int u = 0; u < 3; ++u)
            #pragma unroll
            for (int pm = 0; pm < 4; ++pm)
                twr[u][pm] = tw4[u * 2048 + 4 * t + pm];
        int off[8];
        #pragma unroll
        for (int m = 0; m < 8; ++m) off[m] = swz(8 * t + m);

        #pragma unroll
        for (int q = 0; q < NQ; ++q) {
            float4 r[4][2];
            #pragma unroll
            for (int j = 0; j < 4; ++j) {
                const float4* xr = reinterpret_cast<const float4*>(
                    x + (size_t)(row0 + 4 * q + j) * kN);
                r[j][0] = __ldcs(xr + 2 * t);       // read-once: evict-first
                r[j][1] = __ldcs(xr + 2 * t + 1);
            }
            float4 v[8];
            pack_quad(r, v);
            substages(v, twr);
            float4* B = buf + q * kN;
            #pragma unroll
            for (int m = 0; m < 8; ++m) B[off[m]] = v[m];
        }
    }

    // ---- HOISTED: phase-1 twiddle loads drain L2 latency meanwhile.
    const int b1 = t >> 3, c1 = t & 7;                    // s = 8
    float4 tw1[3][4];
    #pragma unroll
    for (int u = 0; u < 3; ++u)
        #pragma unroll
        for (int pm = 0; pm < 4; ++pm)
            tw1[u][pm] = tw4[(3 + u) * 2048 + 8 * (4 * b1 + pm) + c1];

    // ph0->1 exchange is warp-local: phase-1 reads [256w, 256w+255], which
    // warp w itself wrote in phase 0. No CTA barrier needed.
    __syncwarp();

    // ------------- Phase 1: stages 3..5 (strides 8,16,32), smem -----------
    {
        int off[8];
        #pragma unroll
        for (int m = 0; m < 8; ++m) off[m] = swz(b1 * 64 + c1 + 8 * m);

        // Prefetch the NEXT tile's data into L2 under phases 1-3 compute.
        if (nrow0 >= 0) {
            const char* nb = reinterpret_cast<const char*>(
                x + (size_t)nrow0 * kN);
            #pragma unroll
            for (int k = 0; k < 3; ++k) {
                const int idx = t + 512 * k;
                if (idx < nchunks)
                    prefetch_l2(nb + (size_t)idx * 128);
            }
        }

        #pragma unroll
        for (int q = 0; q < NQ; ++q) {
            float4* B = buf + q * kN;
            float4 v[8];
            #pragma unroll
            for (int m = 0; m < 8; ++m) v[m] = B[off[m]];

            substages(v, tw1);

            #pragma unroll
            for (int m = 0; m < 8; ++m) B[off[m]] = v[m];
        }
    }

    // ---- HOISTED: phase-2 twiddle loads before the pair barrier.
    const int b2 = t >> 6, c2 = t & 63;                   // s = 64
    float4 tw2[3][4];
    #pragma unroll
    for (int u = 0; u < 3; ++u)
        #pragma unroll
        for (int pm = 0; pm < 4; ++pm)
            tw2[u][pm] = tw4[(6 + u) * 2048 + 64 * (4 * b2 + pm) + c2];

    // ph1->2 exchange is warp-pair-local: phase-2 reads [512j, 512j+511],
    // written in phase 1 by warps 2j and 2j+1 only.
    bar_pair(t >> 6);

    // ------------- Phase 2: stages 6..8 (strides 64,128,256), smem --------
    {
        int off[8];
        #pragma unroll
        for (int m = 0; m < 8; ++m) off[m] = swz(b2 * 512 + c2 + 64 * m);

        #pragma unroll
        for (int q = 0; q < NQ; ++q) {
            float4* B = buf + q * kN;
            float4 v[8];
            #pragma unroll
            for (int m = 0; m < 8; ++m) v[m] = B[off[m]];

            substages(v, tw2);

            #pragma unroll
            for (int m = 0; m < 8; ++m) B[off[m]] = v[m];
        }
    }

    // ---- HOISTED: phase-3 twiddle loads before the barrier.
    float4 tw3[3][4];
    #pragma unroll
    for (int u = 0; u < 3; ++u)
        #pragma unroll
        for (int pm = 0; pm < 4; ++pm)
            tw3[u][pm] = tw4[(9 + u) * 2048 + 512 * pm + t];

    __syncthreads();   // ph2->3: stride-512 reads span all of N

    // ------------- Phase 3: stages 9..11 (strides 512..2048) -> out -------
    {
        int off[8];
        #pragma unroll
        for (int m = 0; m < 8; ++m) off[m] = swz(t + 512 * m);

        // Quads 0..NQ-2: read, compute, store.
        #pragma unroll
        for (int q = 0; q < NQ - 1; ++q) {
            float4* B = buf + q * kN;
            float4 v[8];
            #pragma unroll
            for (int m = 0; m < 8; ++m) v[m] = B[off[m]];

            substages(v, tw3);
            store_quad(out, row0 + 4 * q, t, v);
        }

        // Last quad: read smem, THEN the end-of-tile barrier, then compute +
        // store — overlapping the next tile's phase-0 LDGs/twiddle loads.
        {
            float4* B = buf + (NQ - 1) * kN;
            float4 v[8];
            #pragma unroll
            for (int m = 0; m < 8; ++m) v[m] = B[off[m]];

            __syncthreads();   // slots now safe for next tile's phase 0

            substages(v, tw3);
            store_quad(out, row0 + 4 * (NQ - 1), t, v);
        }
    }
}

__global__ void __launch_bounds__(kThreads, 1)
butterfly_kernel(const float* __restrict__ x,
                 const float* __restrict__ tw,
                 float* __restrict__ out) {
    extern __shared__ float4 buf[];

    for (int tile = blockIdx.x; tile < kTiles; tile += kGrid) {
        const int row0  = tile_row0(tile);
        const int nt    = tile + kGrid;
        const int nrow0 = (nt < kTiles) ? tile_row0(nt) : -1;
        const int nchk  = (nt < kTiles) ? tile_rows(nt) * (kN * 4 / 128) : 0;

        if (tile < kTiles12) {
            bf_body<3>(x, tw, out, row0, nrow0, nchk, buf);   // 12-row tile
        } else {
            bf_body<2>(x, tw, out, row0, nrow0, nchk, buf);   // 8-row tile
        }
    }
}

extern "C" void kernel_launch(void* const* d_in, const int* in_sizes, int n_in,
                              void* d_out, int out_size) {
    const float* x  = (const float*)d_in[0];   // (8192, 4096) fp32
    const float* tw = (const float*)d_in[1];   // (1,1,12,2048,2,2) fp32
    float* out      = (float*)d_out;           // (8192, 4096) fp32

    cudaFuncSetAttribute(butterfly_kernel,
                         cudaFuncAttributeMaxDynamicSharedMemorySize, kSmem);
    butterfly_kernel<<<kGrid, kThreads, kSmem>>>(x, tw, out);
}